// round 7
// baseline (speedup 1.0000x reference)
#include <cuda_runtime.h>

// ElevationLoss: tversky(logits, gt) * elevation(softmax, heights, gt)
// B=8, C=2, H=W=512, gt in {0,1}. Single fused kernel, last-block finalize.
// 4x2 pixel tile/thread. All 28 LDGs front-batched; branch-free boundaries
// via a zero row + predicated selects.

#define IMG_H 512
#define IMG_W 512
#define HW (IMG_H * IMG_W)        // 262144
#define NBATCH 8
#define NPIX (NBATCH * HW)        // 2097152
#define NTHREADS (NPIX / 8)       // 262144 (8 px per thread)
#define NT 128
#define NB (NTHREADS / NT)        // 2048 blocks
#define NACC 5

// Per-block partials: [Σp1, inter1, count1, comb_sum, ud_sum]
__device__ float g_part[NB * 8];
__device__ unsigned g_count = 0;               // reset by last block each launch
__device__ __align__(16) float g_zrowf[IMG_W]; // zero-initialized, never written
__device__ __align__(16) int   g_zrowi[IMG_W]; // zero-initialized, never written

__device__ __forceinline__ float block_reduce(float v, float* sh) {
    #pragma unroll
    for (int o = 16; o > 0; o >>= 1) v += __shfl_down_sync(0xffffffffu, v, o);
    int lane = threadIdx.x & 31;
    int w = threadIdx.x >> 5;
    __syncthreads();                 // protect sh reuse across calls
    if (lane == 0) sh[w] = v;
    __syncthreads();
    if (w == 0) {
        v = (lane < NT / 32) ? sh[lane] : 0.0f;
        #pragma unroll
        for (int o = NT / 64; o > 0; o >>= 1)
            v += __shfl_down_sync(0xffffffffu, v, o);
    }
    return v;   // valid in thread 0
}

__global__ __launch_bounds__(NT) void elev_fused(
    const float* __restrict__ pred,   // (B,2,H,W)
    const float* __restrict__ hgt,    // (B,1,H,W)
    const int*   __restrict__ gt,     // (B,1,H,W)
    float* __restrict__ out)
{
    float s_p1 = 0.f, s_i1 = 0.f, s_ud = 0.f;
    int cbi = 0;
    unsigned flm = 0;                 // center-flood bitmask (8 px)

    {
        int g  = blockIdx.x * NT + threadIdx.x;   // exactly NTHREADS threads
        int b  = g >> 15;          // 32768 tiles per image
        int r  = g & 32767;
        int ty = r >> 7;           // 256 tile-rows
        int xg = r & 127;          // 128 tiles per row
        int x0 = xg << 2;
        int y0 = ty << 1;

        const float* pb = pred + ((size_t)b * 2) * HW;
        const float* hb = hgt + (size_t)b * HW;
        const int*   gb = gt  + (size_t)b * HW;

        // Row pointers: OOB rows -> static zero row (reference zero padding).
        const float* hr[4];
        const int*   gr[4];
        #pragma unroll
        for (int k = 0; k < 4; k++) {
            int ry = y0 - 1 + k;
            bool v = (unsigned)ry < (unsigned)IMG_H;
            hr[k] = v ? (hb + (ry << 9)) : g_zrowf;
            gr[k] = v ? (gb + (ry << 9)) : g_zrowi;
        }
        bool lv = (x0 > 0);
        bool rv = (x0 + 4 < IMG_W);
        int  xl = lv ? x0 - 1 : 0;
        int  xr = rv ? x0 + 4 : IMG_W - 1;

        // ---------- front-batched loads (all independent) ----------
        float4 l0a = ((const float4*)pb)[( y0      << 7) + xg];
        float4 l1a = ((const float4*)pb)[(HW >> 2) + (( y0      ) << 7) + xg];
        float4 l0b = ((const float4*)pb)[((y0 + 1) << 7) + xg];
        float4 l1b = ((const float4*)pb)[(HW >> 2) + ((y0 + 1) << 7) + xg];

        int4   gv[4];  float4 hv[4];
        int    gl[4],  grt[4];
        float  hl[4],  hrt[4];
        #pragma unroll
        for (int k = 0; k < 4; k++) {
            gv[k]  = ((const int4*)  gr[k])[xg];
            hv[k]  = ((const float4*)hr[k])[xg];
            gl[k]  = gr[k][xl];  hl[k]  = hr[k][xl];
            grt[k] = gr[k][xr];  hrt[k] = hr[k][xr];
        }
        #pragma unroll
        for (int k = 0; k < 4; k++) {       // edge validity (predicated selects)
            gl[k]  = lv ? gl[k]  : 0;  hl[k]  = lv ? hl[k]  : 0.f;
            grt[k] = rv ? grt[k] : 0;  hrt[k] = rv ? hrt[k] : 0.f;
        }

        // ---------- centers ----------
        float hc[8] = {hv[1].x, hv[1].y, hv[1].z, hv[1].w,
                       hv[2].x, hv[2].y, hv[2].z, hv[2].w};
        flm = (unsigned)gv[1].x | ((unsigned)gv[1].y << 1) |
              ((unsigned)gv[1].z << 2) | ((unsigned)gv[1].w << 3) |
              ((unsigned)gv[2].x << 4) | ((unsigned)gv[2].y << 5) |
              ((unsigned)gv[2].z << 6) | ((unsigned)gv[2].w << 7);

        // ---------- softmax + unified pred + tversky prob partials ----------
        float u[8];
        {
            float t[8] = {l1a.x - l0a.x, l1a.y - l0a.y, l1a.z - l0a.z, l1a.w - l0a.w,
                          l1b.x - l0b.x, l1b.y - l0b.y, l1b.z - l0b.z, l1b.w - l0b.w};
            #pragma unroll
            for (int p = 0; p < 8; p++) {
                float p1 = 1.0f / (1.0f + __expf(-t[p]));
                s_p1 += p1;
                if ((flm >> p) & 1u) s_i1 += p1;
                u[p] = (t[p] > 0.f) ? p1 : p1 - 1.f;
            }
        }

        // ---------- stencil ----------
        // enc = (1<<16) + (1 - nsi), nsi = 2g-1 = -gt_sign; hw = -nsi*h.
        // pair: m = fma(nsi, hc, hw) = gt_sign*(h-hc); pass iff m <= 0.
        // Pass adds enc: hi16 += 1 (cb), lo16 += 1 - nsi (cb + dd).
        int   acc[8] = {0,0,0,0,0,0,0,0};
        int   enc[6];
        float sg[6], hw[6];

        auto build = [&](int k) {
            int   gg[6] = {gl[k], gv[k].x, gv[k].y, gv[k].z, gv[k].w, grt[k]};
            float hh[6] = {hl[k], hv[k].x, hv[k].y, hv[k].z, hv[k].w, hrt[k]};
            #pragma unroll
            for (int j = 0; j < 6; j++) {
                int nsi = 2 * gg[j] - 1;
                enc[j] = 65537 - nsi;
                sg[j]  = (float)nsi;
                hw[j]  = -sg[j] * hh[j];
            }
        };
        auto sten = [&](int pr) {
            #pragma unroll
            for (int px = 0; px < 4; px++) {
                #pragma unroll
                for (int dx = 0; dx < 3; dx++) {
                    int j = px + dx;
                    float m = fmaf(sg[j], hc[pr + px], hw[j]);
                    if (m <= 0.f) acc[pr + px] += enc[j];
                }
            }
        };

        build(1); sten(0); sten(4);      // row y0   -> both pixel rows
        build(2); sten(0); sten(4);      // row y0+1 -> both pixel rows
        build(0); sten(0);               // row y0-1 -> pixel row 0
        build(3); sten(4);               // row y0+2 -> pixel row 1

        #pragma unroll
        for (int p = 0; p < 8; p++) {
            int cb = acc[p] >> 16;
            int dd = (acc[p] & 0xFFFF) - cb;
            cbi += cb;
            s_ud = fmaf(u[p], (float)dd, s_ud);
        }
    }

    // ---- per-block reduction ----
    __shared__ float sh[NT / 32];
    {
        float acc[NACC] = {s_p1, s_i1, (float)__popc(flm), (float)cbi, s_ud};
        #pragma unroll
        for (int k = 0; k < NACC; k++) {
            float r = block_reduce(acc[k], sh);
            if (threadIdx.x == 0) g_part[blockIdx.x * 8 + k] = r;
        }
    }

    // ---- last-block finalize ----
    __shared__ bool is_last;
    if (threadIdx.x == 0) {
        __threadfence();                     // publish this block's partials
        unsigned c = atomicAdd(&g_count, 1u);
        is_last = (c == (unsigned)(NB - 1));
    }
    __syncthreads();
    if (!is_last) return;
    __threadfence();                         // acquire all blocks' partials

    float acc[NACC];
    #pragma unroll
    for (int k = 0; k < NACC; k++) acc[k] = 0.0f;
    for (int i = threadIdx.x; i < NB; i += NT) {
        #pragma unroll
        for (int k = 0; k < NACC; k++) acc[k] += g_part[i * 8 + k];
    }
    float tot[NACC];
    #pragma unroll
    for (int k = 0; k < NACC; k++) tot[k] = block_reduce(acc[k], sh);

    if (threadIdx.x == 0) {
        const float ALPHA = 0.3f, BETA = 0.7f, GAMMA = 1.33f, EPS = 1e-7f;
        float p1s  = tot[0];
        float i1   = tot[1];
        float c1   = tot[2];
        float csum = tot[3];
        float uds  = tot[4];

        float p0s = (float)NPIX - p1s;
        float c0  = (float)NPIX - c1;
        float i0  = (float)NPIX - c1 - p1s + i1;   // sum((1-cf)*(1-p1))

        float fp0 = p0s - i0;
        float fn0 = c0 - i0;
        float d0  = fmaxf(i0 + ALPHA * fp0 + BETA * fn0 + EPS, EPS);
        float loss0 = powf(1.0f - i0 / d0, GAMMA) * (c0 > 0.0f ? 1.0f : 0.0f);

        float fp1 = p1s - i1;
        float fn1 = c1 - i1;
        float d1  = fmaxf(i1 + ALPHA * fp1 + BETA * fn1 + EPS, EPS);
        float loss1 = powf(1.0f - i1 / d1, GAMMA) * (c1 > 0.0f ? 1.0f : 0.0f);

        float tversky = 0.5f * (loss0 + loss1);
        float elev    = (csum + uds) / fmaxf(csum, 1.0f);

        out[0] = tversky * elev;
        g_count = 0;   // reset for next graph replay
    }
}

extern "C" void kernel_launch(void* const* d_in, const int* in_sizes, int n_in,
                              void* d_out, int out_size)
{
    const float* pred = (const float*)d_in[0];   // (8,2,512,512) f32
    const float* hgt  = (const float*)d_in[1];   // (8,1,512,512) f32
    const int*   gt   = (const int*)  d_in[2];   // (8,1,512,512) i32
    float* out = (float*)d_out;

    elev_fused<<<NB, NT>>>(pred, hgt, gt, out);
}